// round 1
// baseline (speedup 1.0000x reference)
#include <cuda_runtime.h>
#include <cuda_bf16.h>
#include <math.h>
#include <stdint.h>

#define BB 64
#define SS 2048
#define HH 1024
#define NEGV -1e10f

__device__ float g_c[BB * HH];        // dec_proj + bias
__device__ float g_logits[BB * SS];   // masked logits scratch

__device__ __forceinline__ uint32_t f2tf32(float x) {
    uint32_t r;
    asm("cvt.rna.tf32.f32 %0, %1;" : "=r"(r) : "f"(x));
    return r;
}

// ---------------------------------------------------------------------------
// Kernel A: c[b][h] = b_attn[h] + sum_k dh[b][k] * Wd[k][h]
// ---------------------------------------------------------------------------
__global__ void dec_proj_kernel(const float* __restrict__ dh,
                                const float* __restrict__ Wa,
                                const float* __restrict__ ba) {
    __shared__ float sdh[HH];
    const int b = blockIdx.y;
    const int h = blockIdx.x * 128 + threadIdx.x;
    for (int i = threadIdx.x; i < HH; i += 128) sdh[i] = dh[b * HH + i];
    __syncthreads();
    float acc = ba[h];
    const float* Wd = Wa;  // first H rows of W_attn
#pragma unroll 8
    for (int k = 0; k < HH; k++) acc += sdh[k] * Wd[(size_t)k * HH + h];
    g_c[b * HH + h] = acc;
}

// ---------------------------------------------------------------------------
// Kernel B: fused enc_proj GEMM + tanh + dot(v) + mask -> logits
// CTA: 128 rows (s) x full H via 8 N-tiles of 128. tf32 mma.sync, fp32 accum.
// ---------------------------------------------------------------------------
__global__ __launch_bounds__(256) void attn_kernel(const float* __restrict__ enc,
                                                   const int* __restrict__ mask,
                                                   const float* __restrict__ Wa,
                                                   const float* __restrict__ vw) {
    __shared__ uint32_t sA[2][128][20];   // [buf][m][k] pad 20 -> conflict-free a-frag loads
    __shared__ uint32_t sB[2][16][136];   // [buf][k][n] pad 136 -> conflict-free b-frag loads
    __shared__ float sC[HH];
    __shared__ float sV[HH];
    __shared__ float sRed[4][128];

    const int tid = threadIdx.x;
    const int b = blockIdx.y;
    const int m0 = blockIdx.x * 128;
    const int lane = tid & 31, wid = tid >> 5;
    const int wm = wid & 1;       // 2 warps along M (64 rows each)
    const int wn = wid >> 1;      // 4 warps along N (32 cols each)
    const int g = lane >> 2, t = lane & 3;

    for (int i = tid; i < HH; i += 256) {
        sC[i] = g_c[b * HH + i];
        sV[i] = vw[i];
    }

    const float* We = Wa + (size_t)HH * HH;
    const float* encb = enc + ((size_t)b * SS + m0) * HH;

    float rowp[8];
#pragma unroll
    for (int i = 0; i < 8; i++) rowp[i] = 0.f;

    for (int nt = 0; nt < 8; nt++) {
        const int n0 = nt * 128;
        float acc[4][4][4];
#pragma unroll
        for (int mi = 0; mi < 4; mi++)
#pragma unroll
            for (int ni = 0; ni < 4; ni++)
#pragma unroll
                for (int e = 0; e < 4; e++) acc[mi][ni][e] = 0.f;

        // load K-tile 0 into buffer 0
#pragma unroll
        for (int i = 0; i < 8; i++) {
            int idx = tid + i * 256;
            int m = idx >> 4, k = idx & 15;
            sA[0][m][k] = f2tf32(encb[(size_t)m * HH + k]);
            int kb = idx >> 7, n = idx & 127;
            sB[0][kb][n] = f2tf32(We[(size_t)kb * HH + n0 + n]);
        }
        __syncthreads();

        for (int kt = 0; kt < 64; kt++) {
            const int buf = kt & 1;
            float ra[8], rb[8];
            if (kt < 63) {
                const int k0 = (kt + 1) * 16;
#pragma unroll
                for (int i = 0; i < 8; i++) {
                    int idx = tid + i * 256;
                    int m = idx >> 4, k = idx & 15;
                    ra[i] = encb[(size_t)m * HH + k0 + k];
                    int kb = idx >> 7, n = idx & 127;
                    rb[i] = We[(size_t)(k0 + kb) * HH + n0 + n];
                }
            }
            // two k8 mma steps on this buffer
#pragma unroll
            for (int ks = 0; ks < 2; ks++) {
                const int kk = ks * 8;
                uint32_t afr[4][4], bfr[4][2];
#pragma unroll
                for (int mi = 0; mi < 4; mi++) {
                    int r = wm * 64 + mi * 16 + g;
                    afr[mi][0] = sA[buf][r][kk + t];
                    afr[mi][1] = sA[buf][r + 8][kk + t];
                    afr[mi][2] = sA[buf][r][kk + t + 4];
                    afr[mi][3] = sA[buf][r + 8][kk + t + 4];
                }
#pragma unroll
                for (int ni = 0; ni < 4; ni++) {
                    int c = wn * 32 + ni * 8 + g;
                    bfr[ni][0] = sB[buf][kk + t][c];
                    bfr[ni][1] = sB[buf][kk + t + 4][c];
                }
#pragma unroll
                for (int mi = 0; mi < 4; mi++)
#pragma unroll
                    for (int ni = 0; ni < 4; ni++)
                        asm volatile(
                            "mma.sync.aligned.m16n8k8.row.col.f32.tf32.tf32.f32 "
                            "{%0,%1,%2,%3}, {%4,%5,%6,%7}, {%8,%9}, {%0,%1,%2,%3};\n"
                            : "+f"(acc[mi][ni][0]), "+f"(acc[mi][ni][1]),
                              "+f"(acc[mi][ni][2]), "+f"(acc[mi][ni][3])
                            : "r"(afr[mi][0]), "r"(afr[mi][1]), "r"(afr[mi][2]),
                              "r"(afr[mi][3]), "r"(bfr[ni][0]), "r"(bfr[ni][1]));
            }
            if (kt < 63) {
                const int nb = buf ^ 1;
#pragma unroll
                for (int i = 0; i < 8; i++) {
                    int idx = tid + i * 256;
                    int m = idx >> 4, k = idx & 15;
                    sA[nb][m][k] = f2tf32(ra[i]);
                    int kb = idx >> 7, n = idx & 127;
                    sB[nb][kb][n] = f2tf32(rb[i]);
                }
            }
            __syncthreads();
        }

        // epilogue: tanh + dot with v, accumulate per-row partials
#pragma unroll
        for (int mi = 0; mi < 4; mi++) {
#pragma unroll
            for (int ni = 0; ni < 4; ni++) {
                const int hbase = n0 + wn * 32 + ni * 8 + 2 * t;
#pragma unroll
                for (int e = 0; e < 4; e++) {
                    int hh = hbase + (e & 1);
                    int p = e >> 1;
                    float val = tanhf(acc[mi][ni][e] + sC[hh]);
                    rowp[mi * 2 + p] += sV[hh] * val;
                }
            }
        }
    }

    // reduce across the 4 lanes sharing a row (t = lane&3)
#pragma unroll
    for (int i = 0; i < 8; i++) {
        rowp[i] += __shfl_xor_sync(0xffffffffu, rowp[i], 1);
        rowp[i] += __shfl_xor_sync(0xffffffffu, rowp[i], 2);
    }
    if (t == 0) {
#pragma unroll
        for (int mi = 0; mi < 4; mi++)
#pragma unroll
            for (int p = 0; p < 2; p++) {
                int r = wm * 64 + mi * 16 + g + p * 8;
                sRed[wn][r] = rowp[mi * 2 + p];
            }
    }
    __syncthreads();
    if (tid < 128) {
        float a = sRed[0][tid] + sRed[1][tid] + sRed[2][tid] + sRed[3][tid];
        int s = m0 + tid;
        if (mask[b * SS + s] == 1) a = NEGV;
        g_logits[b * SS + s] = a;
    }
}

// ---------------------------------------------------------------------------
// Kernel C: softmax over S per batch row
// ---------------------------------------------------------------------------
__global__ void softmax_kernel(float* __restrict__ out) {
    __shared__ float sm[SS];
    __shared__ float red[256];
    const int b = blockIdx.x;
    const int tid = threadIdx.x;
    float mx = -INFINITY;
    for (int i = tid; i < SS; i += 256) {
        float v = g_logits[b * SS + i];
        sm[i] = v;
        mx = fmaxf(mx, v);
    }
    red[tid] = mx;
    __syncthreads();
    for (int o = 128; o > 0; o >>= 1) {
        if (tid < o) red[tid] = fmaxf(red[tid], red[tid + o]);
        __syncthreads();
    }
    mx = red[0];
    __syncthreads();
    float sum = 0.f;
    for (int i = tid; i < SS; i += 256) {
        float e = expf(sm[i] - mx);
        sm[i] = e;
        sum += e;
    }
    red[tid] = sum;
    __syncthreads();
    for (int o = 128; o > 0; o >>= 1) {
        if (tid < o) red[tid] += red[tid + o];
        __syncthreads();
    }
    sum = red[0];
    float inv = 1.0f / sum;
    for (int i = tid; i < SS; i += 256) out[b * SS + i] = sm[i] * inv;
}

extern "C" void kernel_launch(void* const* d_in, const int* in_sizes, int n_in,
                              void* d_out, int out_size) {
    const float* dh   = (const float*)d_in[0];
    const float* enc  = (const float*)d_in[1];
    const int*   mask = (const int*)d_in[2];
    const float* Wa   = (const float*)d_in[3];
    const float* ba   = (const float*)d_in[4];
    const float* vw   = (const float*)d_in[5];
    float* out = (float*)d_out;

    dec_proj_kernel<<<dim3(8, BB), 128>>>(dh, Wa, ba);
    attn_kernel<<<dim3(SS / 128, BB), 256>>>(enc, mask, Wa, vw);
    softmax_kernel<<<BB, 256>>>(out);
}

// round 3
// speedup vs baseline: 1.7996x; 1.7996x over previous
#include <cuda_runtime.h>
#include <math.h>
#include <stdint.h>
#include <stddef.h>

#define BB 64
#define SS 2048
#define HH 1024
#define NEGV -1e10f

// ---------------- tiling ----------------
#define KSTG 32                    // K elems per pipeline stage
#define NT 8                       // 8 N-tiles of 128 = H
#define STG_PER_NT (HH / KSTG)     // 32
#define TOTS (NT * STG_PER_NT)     // 256 stages
#define ASTR 36                    // A smem row stride in floats (bank: 4g+t unique)
#define BSTR 136                   // B smem row stride in floats (bank: 8t+8ni+g unique)
#define ASTG (128 * ASTR * 4)      // 18432 B per A stage
#define BSTG (KSTG * BSTR * 4)     // 17408 B per B stage
#define SC_OFF 0
#define SV_OFF 4096
#define SRED_OFF 8192
#define A_OFF 10240
#define B_OFF (A_OFF + 2 * ASTG)
#define SMEM_TOTAL (B_OFF + 2 * BSTG)   // 81920 bytes

__device__ float g_c[BB * HH];           // dec_proj + bias
__device__ float g_cpart[8 * BB * HH];   // dec_proj k-split partials
__device__ float g_logits[BB * SS];      // masked logits
__device__ float g_WeR[HH * HH];         // We rounded to tf32, layout [k][n]

// ---------------- helpers ----------------
static __device__ __forceinline__ uint32_t f2tf32(float x) {
    uint32_t r;
    asm("cvt.rna.tf32.f32 %0, %1;" : "=r"(r) : "f"(x));
    return r;
}
static __device__ __forceinline__ uint32_t smem_u32(const void* p) {
    uint32_t a;
    asm("{ .reg .u64 t; cvta.to.shared.u64 t, %1; cvt.u32.u64 %0, t; }" : "=r"(a) : "l"(p));
    return a;
}
static __device__ __forceinline__ void cp16(uint32_t d, const void* s) {
    asm volatile("cp.async.cg.shared.global [%0], [%1], 16;" :: "r"(d), "l"(s) : "memory");
}
#define CP_COMMIT() asm volatile("cp.async.commit_group;" ::: "memory")
#define CP_WAIT0()  asm volatile("cp.async.wait_group 0;" ::: "memory")

// ---------------------------------------------------------------------------
// Prep 1: round We into tf32 (same [k][n] layout; no transpose needed for
// mma.sync .col B fragments)
// ---------------------------------------------------------------------------
__global__ void round_we(const float* __restrict__ Wa) {
    const float* We = Wa + (size_t)HH * HH;
    size_t i = (size_t)blockIdx.x * 256 + threadIdx.x;
    g_WeR[i] = __uint_as_float(f2tf32(We[i]));
}

// ---------------------------------------------------------------------------
// Prep 2: dec_proj k-split partials (deterministic, no atomics)
// ---------------------------------------------------------------------------
__global__ void __launch_bounds__(128) decproj_part(const float* __restrict__ dh,
                                                    const float* __restrict__ Wa) {
    __shared__ float sdh[64 * 128];
    const int tid = threadIdx.x;
    const int h = blockIdx.x * 128 + tid;
    const int k0 = blockIdx.y * 128;
    for (int i = tid; i < 64 * 128; i += 128) {
        int b = i >> 7, kk = i & 127;
        sdh[i] = dh[b * HH + k0 + kk];
    }
    __syncthreads();
    float acc[64];
#pragma unroll
    for (int b = 0; b < 64; b++) acc[b] = 0.f;
    for (int kk = 0; kk < 128; kk++) {
        float w = Wa[(size_t)(k0 + kk) * HH + h];
#pragma unroll
        for (int b = 0; b < 64; b++) acc[b] += sdh[b * 128 + kk] * w;
    }
#pragma unroll
    for (int b = 0; b < 64; b++)
        g_cpart[((size_t)blockIdx.y * BB + b) * HH + h] = acc[b];
}

__global__ void decproj_reduce(const float* __restrict__ ba) {
    int b = blockIdx.x;
    for (int h = threadIdx.x; h < HH; h += 256) {
        float s = ba[h];
#pragma unroll
        for (int kc = 0; kc < 8; kc++) s += g_cpart[((size_t)kc * BB + b) * HH + h];
        g_c[b * HH + h] = s;
    }
}

// ---------------------------------------------------------------------------
// Fused main: tf32 mma.sync GEMM + tanh + dot(v) + mask -> logits
// CTA = 128 rows; loops 8 N-tiles of 128; K=1024 via double-buffered cp.async
// stages of K=32; ONE __syncthreads per stage.
// ---------------------------------------------------------------------------
static __device__ __forceinline__ void fill_stage(char* smem, int tid,
                                                  const float* __restrict__ encb,
                                                  int gs, int buf) {
    const int nt = gs >> 5, kt = gs & 31;
    const int k0 = kt * KSTG;
    const int n0 = nt * 128;
    const uint32_t abase = smem_u32(smem + A_OFF + buf * ASTG);
    const uint32_t bbase = smem_u32(smem + B_OFF + buf * BSTG);
    // A: 128 rows x 32 floats = 1024 x 16B units
#pragma unroll
    for (int i = 0; i < 4; i++) {
        int u = tid + i * 256;
        int row = u >> 3, c = u & 7;
        cp16(abase + row * (ASTR * 4) + c * 16,
             encb + (size_t)row * HH + k0 + c * 4);
    }
    // B: 32 rows x 128 floats = 1024 x 16B units
#pragma unroll
    for (int i = 0; i < 4; i++) {
        int u = tid + i * 256;
        int row = u >> 5, c = u & 31;
        cp16(bbase + row * (BSTR * 4) + c * 16,
             g_WeR + (size_t)(k0 + row) * HH + n0 + c * 4);
    }
}

__global__ void __launch_bounds__(256, 2) attn_kernel(const float* __restrict__ enc,
                                                      const int* __restrict__ mask,
                                                      const float* __restrict__ vw) {
    extern __shared__ char smem[];
    float* sC = (float*)(smem + SC_OFF);
    float* sV = (float*)(smem + SV_OFF);
    float* sRed = (float*)(smem + SRED_OFF);

    const int tid = threadIdx.x;
    const int wid = tid >> 5, lane = tid & 31;
    const int wm = wid & 1;        // 2 warps along M (64 rows each)
    const int wn = wid >> 1;       // 4 warps along N (32 cols each)
    const int g = lane >> 2, t = lane & 3;
    const int cta = blockIdx.x;
    const int b = cta >> 4;
    const int m0 = (cta & 15) * 128;
    const float* encb = enc + ((size_t)b * SS + m0) * HH;

    for (int i = tid; i < HH; i += 256) {
        sC[i] = g_c[b * HH + i];
        sV[i] = vw[i];
    }
    __syncthreads();

    float acc[4][4][4];
#pragma unroll
    for (int mi = 0; mi < 4; mi++)
#pragma unroll
        for (int ni = 0; ni < 4; ni++)
#pragma unroll
            for (int e = 0; e < 4; e++) acc[mi][ni][e] = 0.f;
    float rowp[8];
#pragma unroll
    for (int i = 0; i < 8; i++) rowp[i] = 0.f;

    // prologue
    fill_stage(smem, tid, encb, 0, 0);
    CP_COMMIT();

    for (int gs = 0; gs < TOTS; gs++) {
        const int buf = gs & 1;
        CP_WAIT0();
        __syncthreads();   // stage gs data visible; everyone done reading other buf
        if (gs + 1 < TOTS) {
            fill_stage(smem, tid, encb, gs + 1, buf ^ 1);
            CP_COMMIT();
        }
        const float* Ap = (const float*)(smem + A_OFF + buf * ASTG);
        const float* Bp = (const float*)(smem + B_OFF + buf * BSTG);
#pragma unroll
        for (int ks = 0; ks < 4; ks++) {
            const int kk = ks * 8;
            uint32_t afr[4][4], bfr[4][2];
#pragma unroll
            for (int mi = 0; mi < 4; mi++) {
                const int r = wm * 64 + mi * 16 + g;
                afr[mi][0] = f2tf32(Ap[r * ASTR + kk + t]);
                afr[mi][1] = f2tf32(Ap[(r + 8) * ASTR + kk + t]);
                afr[mi][2] = f2tf32(Ap[r * ASTR + kk + t + 4]);
                afr[mi][3] = f2tf32(Ap[(r + 8) * ASTR + kk + t + 4]);
            }
#pragma unroll
            for (int ni = 0; ni < 4; ni++) {
                const int c = wn * 32 + ni * 8 + g;
                bfr[ni][0] = __float_as_uint(Bp[(kk + t) * BSTR + c]);
                bfr[ni][1] = __float_as_uint(Bp[(kk + t + 4) * BSTR + c]);
            }
#pragma unroll
            for (int mi = 0; mi < 4; mi++)
#pragma unroll
                for (int ni = 0; ni < 4; ni++)
                    asm volatile(
                        "mma.sync.aligned.m16n8k8.row.col.f32.tf32.tf32.f32 "
                        "{%0,%1,%2,%3}, {%4,%5,%6,%7}, {%8,%9}, {%0,%1,%2,%3};\n"
                        : "+f"(acc[mi][ni][0]), "+f"(acc[mi][ni][1]),
                          "+f"(acc[mi][ni][2]), "+f"(acc[mi][ni][3])
                        : "r"(afr[mi][0]), "r"(afr[mi][1]), "r"(afr[mi][2]),
                          "r"(afr[mi][3]), "r"(bfr[ni][0]), "r"(bfr[ni][1]));
        }
        if ((gs & 31) == 31) {
            // epilogue for this N-tile: tanh + dot(v); registers + read-only smem only
            const int nt = gs >> 5;
            const int n0 = nt * 128;
#pragma unroll
            for (int mi = 0; mi < 4; mi++)
#pragma unroll
                for (int ni = 0; ni < 4; ni++) {
                    const int hbase = n0 + wn * 32 + ni * 8 + 2 * t;
#pragma unroll
                    for (int e = 0; e < 4; e++) {
                        const int hh = hbase + (e & 1);
                        const int p = e >> 1;
                        rowp[mi * 2 + p] += sV[hh] * tanhf(acc[mi][ni][e] + sC[hh]);
                        acc[mi][ni][e] = 0.f;
                    }
                }
        }
    }

    // reduce across the 4 lanes sharing each row
#pragma unroll
    for (int i = 0; i < 8; i++) {
        rowp[i] += __shfl_xor_sync(0xffffffffu, rowp[i], 1);
        rowp[i] += __shfl_xor_sync(0xffffffffu, rowp[i], 2);
    }
    __syncthreads();
    if (t == 0) {
#pragma unroll
        for (int mi = 0; mi < 4; mi++)
#pragma unroll
            for (int p = 0; p < 2; p++) {
                const int r = wm * 64 + mi * 16 + g + p * 8;
                sRed[wn * 128 + r] = rowp[mi * 2 + p];
            }
    }
    __syncthreads();
    if (tid < 128) {
        float a = sRed[tid] + sRed[128 + tid] + sRed[256 + tid] + sRed[384 + tid];
        const int s = m0 + tid;
        if (mask[b * SS + s] == 1) a = NEGV;
        g_logits[b * SS + s] = a;
    }
}

// ---------------------------------------------------------------------------
// Softmax over S per batch row
// ---------------------------------------------------------------------------
__global__ void softmax_kernel(float* __restrict__ out) {
    __shared__ float sm[SS];
    __shared__ float red[256];
    const int b = blockIdx.x;
    const int tid = threadIdx.x;
    float mx = -INFINITY;
    for (int i = tid; i < SS; i += 256) {
        float v = g_logits[b * SS + i];
        sm[i] = v;
        mx = fmaxf(mx, v);
    }
    red[tid] = mx;
    __syncthreads();
    for (int o = 128; o > 0; o >>= 1) {
        if (tid < o) red[tid] = fmaxf(red[tid], red[tid + o]);
        __syncthreads();
    }
    mx = red[0];
    __syncthreads();
    float sum = 0.f;
    for (int i = tid; i < SS; i += 256) {
        float e = expf(sm[i] - mx);
        sm[i] = e;
        sum += e;
    }
    red[tid] = sum;
    __syncthreads();
    for (int o = 128; o > 0; o >>= 1) {
        if (tid < o) red[tid] += red[tid + o];
        __syncthreads();
    }
    const float inv = 1.0f / red[0];
    for (int i = tid; i < SS; i += 256) out[b * SS + i] = sm[i] * inv;
}

extern "C" void kernel_launch(void* const* d_in, const int* in_sizes, int n_in,
                              void* d_out, int out_size) {
    const float* dh   = (const float*)d_in[0];
    const float* enc  = (const float*)d_in[1];
    const int*   mask = (const int*)d_in[2];
    const float* Wa   = (const float*)d_in[3];
    const float* ba   = (const float*)d_in[4];
    const float* vw   = (const float*)d_in[5];
    float* out = (float*)d_out;

    cudaFuncSetAttribute(attn_kernel, cudaFuncAttributeMaxDynamicSharedMemorySize, SMEM_TOTAL);

    round_we<<<HH * HH / 256, 256>>>(Wa);
    decproj_part<<<dim3(8, 8), 128>>>(dh, Wa);
    decproj_reduce<<<BB, 256>>>(ba);
    attn_kernel<<<1024, 256, SMEM_TOTAL>>>(enc, mask, vw);
    softmax_kernel<<<BB, 256>>>(out);
}

// round 4
// speedup vs baseline: 1.9216x; 1.0678x over previous
#include <cuda_runtime.h>
#include <math.h>
#include <stdint.h>
#include <stddef.h>

#define BB 64
#define SS 2048
#define HH 1024
#define NEGV -1e10f

// ---------------- tiling ----------------
#define KSTG 32                    // K elems per pipeline stage
#define NT 8                       // 8 N-tiles of 128 = H
#define TOTS (NT * (HH / KSTG))    // 256 stages
#define ASTR 36                    // A smem row stride (floats); 144B = 9x16B -> LDSM bank-clean
#define BSTR 136                   // B smem row stride (floats); 136%32=8 -> LDS.128 bank-clean
#define ASTG (128 * ASTR * 4)      // 18432 B per A stage
#define BSTG (KSTG * BSTR * 4)     // 17408 B per B stage
#define SC_OFF 0
#define SV_OFF 4096
#define SRED_OFF 8192
#define A_OFF 10240
#define B_OFF (A_OFF + 2 * ASTG)
#define SMEM_TOTAL (B_OFF + 2 * BSTG)   // 81920 bytes

__device__ float g_c[BB * HH];           // dec_proj + bias
__device__ float g_cpart[8 * BB * HH];   // dec_proj k-split partials
__device__ float g_logits[BB * SS];      // masked logits
__device__ float g_WeR[HH * HH];         // We: tf32-rounded, column-PERMUTED [k][cc]

// ---------------- helpers ----------------
static __device__ __forceinline__ uint32_t f2tf32(float x) {
    uint32_t r;
    asm("cvt.rna.tf32.f32 %0, %1;" : "=r"(r) : "f"(x));
    return r;
}
static __device__ __forceinline__ uint32_t smem_u32(const void* p) {
    uint32_t a;
    asm("{ .reg .u64 t; cvta.to.shared.u64 t, %1; cvt.u32.u64 %0, t; }" : "=r"(a) : "l"(p));
    return a;
}
static __device__ __forceinline__ void cp16(uint32_t d, const void* s) {
    asm volatile("cp.async.cg.shared.global [%0], [%1], 16;" :: "r"(d), "l"(s) : "memory");
}
#define CP_COMMIT() asm volatile("cp.async.commit_group;" ::: "memory")
#define CP_WAIT0()  asm volatile("cp.async.wait_group 0;" ::: "memory")

// ---------------------------------------------------------------------------
// Prep 1: g_WeR[k][cc] = rna_tf32(We[k][perm(cc)]) where within each 32-col
// group: cc = g*4 + ni  <->  logical n = ni*8 + g  (g:0..7, ni:0..3)
// ---------------------------------------------------------------------------
__global__ void round_we(const float* __restrict__ Wa) {
    const float* We = Wa + (size_t)HH * HH;
    size_t i = (size_t)blockIdx.x * 256 + threadIdx.x;   // k*HH + n (logical)
    int n = (int)(i & (HH - 1));
    int grp = n & ~31;
    int r = n & 31;
    int g = r & 7, ni = r >> 3;
    int cc = grp + g * 4 + ni;
    size_t k = i >> 10;
    g_WeR[k * HH + cc] = __uint_as_float(f2tf32(We[i]));
}

// ---------------------------------------------------------------------------
// Prep 2: dec_proj k-split partials (deterministic, no atomics)
// ---------------------------------------------------------------------------
__global__ void __launch_bounds__(128) decproj_part(const float* __restrict__ dh,
                                                    const float* __restrict__ Wa) {
    __shared__ float sdh[64 * 128];
    const int tid = threadIdx.x;
    const int h = blockIdx.x * 128 + tid;
    const int k0 = blockIdx.y * 128;
    for (int i = tid; i < 64 * 128; i += 128) {
        int b = i >> 7, kk = i & 127;
        sdh[i] = dh[b * HH + k0 + kk];
    }
    __syncthreads();
    float acc[64];
#pragma unroll
    for (int b = 0; b < 64; b++) acc[b] = 0.f;
    for (int kk = 0; kk < 128; kk++) {
        float w = Wa[(size_t)(k0 + kk) * HH + h];
#pragma unroll
        for (int b = 0; b < 64; b++) acc[b] += sdh[b * 128 + kk] * w;
    }
#pragma unroll
    for (int b = 0; b < 64; b++)
        g_cpart[((size_t)blockIdx.y * BB + b) * HH + h] = acc[b];
}

__global__ void decproj_reduce(const float* __restrict__ ba) {
    int b = blockIdx.x;
    for (int h = threadIdx.x; h < HH; h += 256) {
        float s = ba[h];
#pragma unroll
        for (int kc = 0; kc < 8; kc++) s += g_cpart[((size_t)kc * BB + b) * HH + h];
        g_c[b * HH + h] = s;
    }
}

// ---------------------------------------------------------------------------
// Fused main: tf32 mma.sync + tanh + dot(v) + mask
// A fragments via ldmatrix.x4 (b32 trick), B via LDS.128 (permuted cols).
// ---------------------------------------------------------------------------
static __device__ __forceinline__ void fill_stage(char* smem, int tid,
                                                  const float* __restrict__ encb,
                                                  int gs, int buf) {
    const int nt = gs >> 5, kt = gs & 31;
    const int k0 = kt * KSTG;
    const int n0 = nt * 128;
    const uint32_t abase = smem_u32(smem + A_OFF + buf * ASTG);
    const uint32_t bbase = smem_u32(smem + B_OFF + buf * BSTG);
    // A: 128 rows x 32 floats = 1024 x16B
#pragma unroll
    for (int i = 0; i < 4; i++) {
        int u = tid + i * 256;
        int row = u >> 3, c = u & 7;
        cp16(abase + row * (ASTR * 4) + c * 16,
             encb + (size_t)row * HH + k0 + c * 4);
    }
    // B: 32 rows x 128 floats = 1024 x16B (g_WeR already permuted+rounded)
#pragma unroll
    for (int i = 0; i < 4; i++) {
        int u = tid + i * 256;
        int row = u >> 5, c = u & 31;
        cp16(bbase + row * (BSTR * 4) + c * 16,
             g_WeR + (size_t)(k0 + row) * HH + n0 + c * 4);
    }
}

__global__ void __launch_bounds__(256, 2) attn_kernel(const float* __restrict__ enc,
                                                      const int* __restrict__ mask,
                                                      const float* __restrict__ vw) {
    extern __shared__ char smem[];
    float* sC = (float*)(smem + SC_OFF);
    float* sV = (float*)(smem + SV_OFF);
    float* sRed = (float*)(smem + SRED_OFF);

    const int tid = threadIdx.x;
    const int wid = tid >> 5, lane = tid & 31;
    const int wm = wid & 1;        // 2 warps along M
    const int wn = wid >> 1;       // 4 warps along N
    const int g = lane >> 2, t = lane & 3;
    const int cta = blockIdx.x;
    const int b = cta >> 4;
    const int m0 = (cta & 15) * 128;
    const float* encb = enc + ((size_t)b * SS + m0) * HH;

    // ldmatrix per-lane source row/col offsets (x4: 4 tiles of 8 rows)
    const int ltile = lane >> 3, lrow = lane & 7;
    const int lm_row = (ltile & 1) * 8 + lrow;     // +0/+8 row
    const int lm_col = (ltile >> 1) * 4;           // +0/+4 k-col

    for (int i = tid; i < HH; i += 256) {
        sC[i] = g_c[b * HH + i];
        sV[i] = vw[i];
    }
    __syncthreads();

    float acc[4][4][4];
#pragma unroll
    for (int mi = 0; mi < 4; mi++)
#pragma unroll
        for (int ni = 0; ni < 4; ni++)
#pragma unroll
            for (int e = 0; e < 4; e++) acc[mi][ni][e] = 0.f;
    float rowp[8];
#pragma unroll
    for (int i = 0; i < 8; i++) rowp[i] = 0.f;

    fill_stage(smem, tid, encb, 0, 0);
    CP_COMMIT();

    for (int gs = 0; gs < TOTS; gs++) {
        const int buf = gs & 1;
        CP_WAIT0();
        __syncthreads();
        if (gs + 1 < TOTS) {
            fill_stage(smem, tid, encb, gs + 1, buf ^ 1);
            CP_COMMIT();
        }
        const uint32_t abase = smem_u32(smem + A_OFF + buf * ASTG);
        const float* Bp = (const float*)(smem + B_OFF + buf * BSTG);
        // per-mi ldmatrix base address (bytes), ks adds kk*4
        uint32_t a_addr[4];
#pragma unroll
        for (int mi = 0; mi < 4; mi++)
            a_addr[mi] = abase + ((wm * 64 + mi * 16 + lm_row) * ASTR + lm_col) * 4;
        const float* brow0 = Bp + t * BSTR + wn * 32 + g * 4;

#pragma unroll
        for (int ks = 0; ks < 4; ks++) {
            const int kk = ks * 8;
            uint32_t afr[4][4];
#pragma unroll
            for (int mi = 0; mi < 4; mi++)
                asm volatile(
                    "ldmatrix.sync.aligned.m8n8.x4.shared.b16 {%0,%1,%2,%3}, [%4];"
                    : "=r"(afr[mi][0]), "=r"(afr[mi][1]),
                      "=r"(afr[mi][2]), "=r"(afr[mi][3])
                    : "r"(a_addr[mi] + kk * 4));
            const uint4 bv0 = *reinterpret_cast<const uint4*>(brow0 + kk * BSTR);
            const uint4 bv1 = *reinterpret_cast<const uint4*>(brow0 + (kk + 4) * BSTR);
            const uint32_t b0[4] = {bv0.x, bv0.y, bv0.z, bv0.w};
            const uint32_t b1[4] = {bv1.x, bv1.y, bv1.z, bv1.w};
#pragma unroll
            for (int mi = 0; mi < 4; mi++)
#pragma unroll
                for (int ni = 0; ni < 4; ni++)
                    asm volatile(
                        "mma.sync.aligned.m16n8k8.row.col.f32.tf32.tf32.f32 "
                        "{%0,%1,%2,%3}, {%4,%5,%6,%7}, {%8,%9}, {%0,%1,%2,%3};\n"
                        : "+f"(acc[mi][ni][0]), "+f"(acc[mi][ni][1]),
                          "+f"(acc[mi][ni][2]), "+f"(acc[mi][ni][3])
                        : "r"(afr[mi][0]), "r"(afr[mi][1]), "r"(afr[mi][2]),
                          "r"(afr[mi][3]), "r"(b0[ni]), "r"(b1[ni]));
        }
        if ((gs & 31) == 31) {
            const int n0 = (gs >> 5) * 128;
#pragma unroll
            for (int mi = 0; mi < 4; mi++)
#pragma unroll
                for (int ni = 0; ni < 4; ni++) {
                    const int hbase = n0 + wn * 32 + ni * 8 + 2 * t;
#pragma unroll
                    for (int e = 0; e < 4; e++) {
                        const int hh = hbase + (e & 1);
                        const int p = e >> 1;
                        rowp[mi * 2 + p] += sV[hh] * tanhf(acc[mi][ni][e] + sC[hh]);
                        acc[mi][ni][e] = 0.f;
                    }
                }
        }
    }

    // reduce the 4 lanes sharing each row
#pragma unroll
    for (int i = 0; i < 8; i++) {
        rowp[i] += __shfl_xor_sync(0xffffffffu, rowp[i], 1);
        rowp[i] += __shfl_xor_sync(0xffffffffu, rowp[i], 2);
    }
    __syncthreads();
    if (t == 0) {
#pragma unroll
        for (int mi = 0; mi < 4; mi++)
#pragma unroll
            for (int p = 0; p < 2; p++) {
                const int r = wm * 64 + mi * 16 + g + p * 8;
                sRed[wn * 128 + r] = rowp[mi * 2 + p];
            }
    }
    __syncthreads();
    if (tid < 128) {
        float a = sRed[tid] + sRed[128 + tid] + sRed[256 + tid] + sRed[384 + tid];
        const int s = m0 + tid;
        if (mask[b * SS + s] == 1) a = NEGV;
        g_logits[b * SS + s] = a;
    }
}

// ---------------------------------------------------------------------------
// Softmax over S per batch row
// ---------------------------------------------------------------------------
__global__ void softmax_kernel(float* __restrict__ out) {
    __shared__ float sm[SS];
    __shared__ float red[256];
    const int b = blockIdx.x;
    const int tid = threadIdx.x;
    float mx = -INFINITY;
    for (int i = tid; i < SS; i += 256) {
        float v = g_logits[b * SS + i];
        sm[i] = v;
        mx = fmaxf(mx, v);
    }
    red[tid] = mx;
    __syncthreads();
    for (int o = 128; o > 0; o >>= 1) {
        if (tid < o) red[tid] = fmaxf(red[tid], red[tid + o]);
        __syncthreads();
    }
    mx = red[0];
    __syncthreads();
    float sum = 0.f;
    for (int i = tid; i < SS; i += 256) {
        float e = expf(sm[i] - mx);
        sm[i] = e;
        sum += e;
    }
    red[tid] = sum;
    __syncthreads();
    for (int o = 128; o > 0; o >>= 1) {
        if (tid < o) red[tid] += red[tid + o];
        __syncthreads();
    }
    const float inv = 1.0f / red[0];
    for (int i = tid; i < SS; i += 256) out[b * SS + i] = sm[i] * inv;
}

extern "C" void kernel_launch(void* const* d_in, const int* in_sizes, int n_in,
                              void* d_out, int out_size) {
    const float* dh   = (const float*)d_in[0];
    const float* enc  = (const float*)d_in[1];
    const int*   mask = (const int*)d_in[2];
    const float* Wa   = (const float*)d_in[3];
    const float* ba   = (const float*)d_in[4];
    const float* vw   = (const float*)d_in[5];
    float* out = (float*)d_out;

    cudaFuncSetAttribute(attn_kernel, cudaFuncAttributeMaxDynamicSharedMemorySize, SMEM_TOTAL);

    round_we<<<HH * HH / 256, 256>>>(Wa);
    decproj_part<<<dim3(8, 8), 128>>>(dh, Wa);
    decproj_reduce<<<BB, 256>>>(ba);
    attn_kernel<<<1024, 256, SMEM_TOTAL>>>(enc, mask, vw);
    softmax_kernel<<<BB, 256>>>(out);
}